// round 4
// baseline (speedup 1.0000x reference)
#include <cuda_runtime.h>
#include <cuda_bf16.h>
#include <math.h>

// Problem constants
#define B_ 4
#define S_ 4096
#define D_ 1024
#define M_ (B_*S_)          // 16384 total rows
#define HALF_D (D_/2)       // 512 rope pairs

// GEMM tiling
#define BM 128
#define BN 128
#define BK 16
#define TM 8
#define TN 8
#define NTHREADS 256

// -------- scratch (static device globals; no allocation at runtime) --------
__device__ float g_q[(size_t)M_ * D_];          // 64 MB (rotated Q)
__device__ float g_k[(size_t)M_ * D_];          // 64 MB (rotated K)
__device__ float g_v[(size_t)M_ * D_];          // 64 MB
__device__ float g_s[(size_t)B_ * S_ * S_];     // 256 MB (scores, then P in-place)
__device__ float g_cos[(size_t)S_ * HALF_D];    // 8 MB
__device__ float g_sin[(size_t)S_ * HALF_D];    // 8 MB

// ---------------------------------------------------------------------------
// Kernel 0: RoPE cos/sin table.
// theta = 10000 ** (-2*(i-1)/d)  (faithful to the reference's i-1).
// Angle is rounded to fp32 exactly as the reference does (pos_f32 * theta_f32),
// then range-reduced in double so sinf/cosf stay accurate even under fast-math.
// ---------------------------------------------------------------------------
__global__ __launch_bounds__(256) void rope_table_kernel() {
    int idx = blockIdx.x * 256 + threadIdx.x;
    if (idx >= S_ * HALF_D) return;
    int pos = idx / HALF_D;
    int i   = idx % HALF_D;
    double ex    = (-2.0 * ((double)i - 1.0)) / (double)D_;
    double theta = exp(ex * 9.210340371976184);          // ln(10000)
    float  thetaf = (float)theta;
    float  angf   = (float)pos * thetaf;                  // fp32, like reference
    double r = fmod((double)angf, 6.283185307179586477);  // exact-ish mod 2pi
    float  rf = (float)r;
    if (rf > 3.14159265358979f) rf -= 6.28318530717959f;  // keep |x| small
    g_cos[idx] = cosf(rf);
    g_sin[idx] = sinf(rf);
}

// ---------------------------------------------------------------------------
// Kernel 1: fused QKV projection + RoPE epilogue for Q/K.
// C[m,n] = sum_k X[m,k] * W[n,k]   (nn.Linear: y = x W^T)
// blockIdx.z: 0->Q(+rope), 1->K(+rope), 2->V
// ---------------------------------------------------------------------------
__global__ __launch_bounds__(NTHREADS) void qkv_rope_kernel(
    const float* __restrict__ x, const float* __restrict__ wq,
    const float* __restrict__ wk, const float* __restrict__ wv)
{
    const int which = blockIdx.z;
    const float* __restrict__ w = (which == 0) ? wq : (which == 1) ? wk : wv;
    float* __restrict__ out     = (which == 0) ? g_q : (which == 1) ? g_k : g_v;

    const int m0 = blockIdx.y * BM;
    const int n0 = blockIdx.x * BN;

    __shared__ float As[BK][BM + 4];
    __shared__ float Bs[BK][BN + 4];

    const int tid = threadIdx.x;
    const int tx  = tid & 15;
    const int ty  = tid >> 4;

    float acc[TM][TN];
#pragma unroll
    for (int i = 0; i < TM; i++)
#pragma unroll
        for (int j = 0; j < TN; j++) acc[i][j] = 0.f;

    for (int k0 = 0; k0 < D_; k0 += BK) {
#pragma unroll
        for (int l = 0; l < 2; l++) {
            int idx = tid + l * NTHREADS;          // 0..511
            int row = idx >> 2;                    // 0..127
            int kq  = (idx & 3) * 4;               // 0,4,8,12
            float4 a = *reinterpret_cast<const float4*>(
                &x[(size_t)(m0 + row) * D_ + k0 + kq]);
            As[kq + 0][row] = a.x; As[kq + 1][row] = a.y;
            As[kq + 2][row] = a.z; As[kq + 3][row] = a.w;
            float4 b = *reinterpret_cast<const float4*>(
                &w[(size_t)(n0 + row) * D_ + k0 + kq]);
            Bs[kq + 0][row] = b.x; Bs[kq + 1][row] = b.y;
            Bs[kq + 2][row] = b.z; Bs[kq + 3][row] = b.w;
        }
        __syncthreads();
#pragma unroll
        for (int kk = 0; kk < BK; kk++) {
            float4 a0 = *reinterpret_cast<const float4*>(&As[kk][ty * TM]);
            float4 a1 = *reinterpret_cast<const float4*>(&As[kk][ty * TM + 4]);
            float4 b0 = *reinterpret_cast<const float4*>(&Bs[kk][tx * TN]);
            float4 b1 = *reinterpret_cast<const float4*>(&Bs[kk][tx * TN + 4]);
            float a[TM] = {a0.x, a0.y, a0.z, a0.w, a1.x, a1.y, a1.z, a1.w};
            float b[TN] = {b0.x, b0.y, b0.z, b0.w, b1.x, b1.y, b1.z, b1.w};
#pragma unroll
            for (int i = 0; i < TM; i++)
#pragma unroll
                for (int j = 0; j < TN; j++) acc[i][j] += a[i] * b[j];
        }
        __syncthreads();
    }

    if (which < 2) {
        // RoPE: out[2i] = e*c + o*s ; out[2i+1] = -e*s + o*c
#pragma unroll
        for (int i = 0; i < TM; i++) {
            int row = m0 + ty * TM + i;
            int pos = row & (S_ - 1);
            const float* crow = g_cos + (size_t)pos * HALF_D;
            const float* srow = g_sin + (size_t)pos * HALF_D;
#pragma unroll
            for (int t = 0; t < TN / 2; t++) {
                int ip = (n0 + tx * TN) / 2 + t;
                float c = crow[ip], s = srow[ip];
                float e = acc[i][2 * t], o = acc[i][2 * t + 1];
                acc[i][2 * t]     =  e * c + o * s;
                acc[i][2 * t + 1] = -e * s + o * c;
            }
        }
    }

#pragma unroll
    for (int i = 0; i < TM; i++) {
        size_t off = (size_t)(m0 + ty * TM + i) * D_ + n0 + tx * TN;
        *reinterpret_cast<float4*>(&out[off]) =
            make_float4(acc[i][0], acc[i][1], acc[i][2], acc[i][3]);
        *reinterpret_cast<float4*>(&out[off + 4]) =
            make_float4(acc[i][4], acc[i][5], acc[i][6], acc[i][7]);
    }
}

// ---------------------------------------------------------------------------
// Kernel 2: causal scores. Only lower-triangular 128x128 tiles are launched
// (triangular index -> (qt,kt)). Masked entries get -1e30.
// ---------------------------------------------------------------------------
#define NTRI ((S_/BM) * (S_/BM + 1) / 2)   // 528 tiles per batch

__global__ __launch_bounds__(NTHREADS) void scores_kernel() {
    const int idx = blockIdx.x;
    const int b   = blockIdx.y;
    int qt = (int)((sqrtf(8.f * (float)idx + 1.f) - 1.f) * 0.5f);
    while ((qt + 1) * (qt + 2) / 2 <= idx) qt++;
    while (qt * (qt + 1) / 2 > idx) qt--;
    const int kt = idx - qt * (qt + 1) / 2;

    const float* __restrict__ Qb = g_q + (size_t)b * S_ * D_;
    const float* __restrict__ Kb = g_k + (size_t)b * S_ * D_;
    const int m0 = qt * BM;
    const int n0 = kt * BN;

    __shared__ float As[BK][BM + 4];
    __shared__ float Bs[BK][BN + 4];

    const int tid = threadIdx.x;
    const int tx  = tid & 15;
    const int ty  = tid >> 4;

    float acc[TM][TN];
#pragma unroll
    for (int i = 0; i < TM; i++)
#pragma unroll
        for (int j = 0; j < TN; j++) acc[i][j] = 0.f;

    for (int k0 = 0; k0 < D_; k0 += BK) {
#pragma unroll
        for (int l = 0; l < 2; l++) {
            int li  = tid + l * NTHREADS;
            int row = li >> 2;
            int kq  = (li & 3) * 4;
            float4 a = *reinterpret_cast<const float4*>(
                &Qb[(size_t)(m0 + row) * D_ + k0 + kq]);
            As[kq + 0][row] = a.x; As[kq + 1][row] = a.y;
            As[kq + 2][row] = a.z; As[kq + 3][row] = a.w;
            float4 bv = *reinterpret_cast<const float4*>(
                &Kb[(size_t)(n0 + row) * D_ + k0 + kq]);
            Bs[kq + 0][row] = bv.x; Bs[kq + 1][row] = bv.y;
            Bs[kq + 2][row] = bv.z; Bs[kq + 3][row] = bv.w;
        }
        __syncthreads();
#pragma unroll
        for (int kk = 0; kk < BK; kk++) {
            float4 a0 = *reinterpret_cast<const float4*>(&As[kk][ty * TM]);
            float4 a1 = *reinterpret_cast<const float4*>(&As[kk][ty * TM + 4]);
            float4 b0 = *reinterpret_cast<const float4*>(&Bs[kk][tx * TN]);
            float4 b1 = *reinterpret_cast<const float4*>(&Bs[kk][tx * TN + 4]);
            float a[TM] = {a0.x, a0.y, a0.z, a0.w, a1.x, a1.y, a1.z, a1.w};
            float bb[TN] = {b0.x, b0.y, b0.z, b0.w, b1.x, b1.y, b1.z, b1.w};
#pragma unroll
            for (int i = 0; i < TM; i++)
#pragma unroll
                for (int j = 0; j < TN; j++) acc[i][j] += a[i] * bb[j];
        }
        __syncthreads();
    }

    const float scale = 0.03125f;   // 1/sqrt(1024)
    float* Srow = g_s + (size_t)b * S_ * S_;
#pragma unroll
    for (int i = 0; i < TM; i++) {
        int q = m0 + ty * TM + i;
#pragma unroll
        for (int j = 0; j < TN; j++) {
            int k = n0 + tx * TN + j;
            float v = acc[i][j] * scale;
            acc[i][j] = (k > q) ? -1e30f : v;   // only happens on diag tile
        }
        size_t off = (size_t)q * S_ + n0 + tx * TN;
        *reinterpret_cast<float4*>(&Srow[off]) =
            make_float4(acc[i][0], acc[i][1], acc[i][2], acc[i][3]);
        *reinterpret_cast<float4*>(&Srow[off + 4]) =
            make_float4(acc[i][4], acc[i][5], acc[i][6], acc[i][7]);
    }
}

// ---------------------------------------------------------------------------
// Kernel 3: per-row softmax, in place. One block per row. Masked entries
// (-1e30) underflow to exact 0.0, which also zero-pads the diagonal tile
// so the PV GEMM can run to a 128-aligned K bound.
// ---------------------------------------------------------------------------
__global__ __launch_bounds__(256) void softmax_kernel() {
    const int rowid = blockIdx.x;
    const int b = rowid >> 12;           // /S_
    const int q = rowid & (S_ - 1);
    float* srow = g_s + (size_t)b * S_ * S_ + (size_t)q * S_;
    const int kmax = ((q >> 7) + 1) << 7;   // round up to 128 tile bound
    const int tid = threadIdx.x;

    float vals[16];
    int nch = 0;
    float mx = -1e30f;
    for (int c = tid * 4; c < kmax; c += 1024) {
        float4 v = *reinterpret_cast<const float4*>(&srow[c]);
        vals[nch * 4 + 0] = v.x; vals[nch * 4 + 1] = v.y;
        vals[nch * 4 + 2] = v.z; vals[nch * 4 + 3] = v.w;
        mx = fmaxf(mx, fmaxf(fmaxf(v.x, v.y), fmaxf(v.z, v.w)));
        nch++;
    }

    __shared__ float red[256];
    red[tid] = mx;
    __syncthreads();
    for (int off = 128; off > 0; off >>= 1) {
        if (tid < off) red[tid] = fmaxf(red[tid], red[tid + off]);
        __syncthreads();
    }
    const float m = red[0];
    __syncthreads();

    float sum = 0.f;
    for (int t = 0; t < nch * 4; t++) {
        vals[t] = __expf(vals[t] - m);
        sum += vals[t];
    }
    red[tid] = sum;
    __syncthreads();
    for (int off = 128; off > 0; off >>= 1) {
        if (tid < off) red[tid] += red[tid + off];
        __syncthreads();
    }
    const float invl = 1.f / red[0];

    int ch = 0;
    for (int c = tid * 4; c < kmax; c += 1024) {
        float4 o = make_float4(vals[ch * 4 + 0] * invl, vals[ch * 4 + 1] * invl,
                               vals[ch * 4 + 2] * invl, vals[ch * 4 + 3] * invl);
        *reinterpret_cast<float4*>(&srow[c]) = o;
        ch++;
    }
}

// ---------------------------------------------------------------------------
// Kernel 4: O = P @ V, causal K bound per query tile.
// ---------------------------------------------------------------------------
__global__ __launch_bounds__(NTHREADS) void pv_kernel(float* __restrict__ out) {
    const int b  = blockIdx.z;
    const int q0 = blockIdx.y * BM;
    const int n0 = blockIdx.x * BN;
    const int kmax = q0 + BM;

    const float* __restrict__ P = g_s + (size_t)b * S_ * S_;
    const float* __restrict__ V = g_v + (size_t)b * S_ * D_;

    __shared__ float As[BK][BM + 4];
    __shared__ float Bs[BK][BN + 4];

    const int tid = threadIdx.x;
    const int tx  = tid & 15;
    const int ty  = tid >> 4;

    float acc[TM][TN];
#pragma unroll
    for (int i = 0; i < TM; i++)
#pragma unroll
        for (int j = 0; j < TN; j++) acc[i][j] = 0.f;

    for (int k0 = 0; k0 < kmax; k0 += BK) {
#pragma unroll
        for (int l = 0; l < 2; l++) {
            int li  = tid + l * NTHREADS;       // 0..511
            int row = li >> 2;                  // 0..127 (query rows)
            int kq  = (li & 3) * 4;
            float4 a = *reinterpret_cast<const float4*>(
                &P[(size_t)(q0 + row) * S_ + k0 + kq]);
            As[kq + 0][row] = a.x; As[kq + 1][row] = a.y;
            As[kq + 2][row] = a.z; As[kq + 3][row] = a.w;

            int krow = li >> 5;                 // 0..15
            int nq   = (li & 31) * 4;           // 0..124
            float4 bv = *reinterpret_cast<const float4*>(
                &V[(size_t)(k0 + krow) * D_ + n0 + nq]);
            *reinterpret_cast<float4*>(&Bs[krow][nq]) = bv;
        }
        __syncthreads();
#pragma unroll
        for (int kk = 0; kk < BK; kk++) {
            float4 a0 = *reinterpret_cast<const float4*>(&As[kk][ty * TM]);
            float4 a1 = *reinterpret_cast<const float4*>(&As[kk][ty * TM + 4]);
            float4 b0 = *reinterpret_cast<const float4*>(&Bs[kk][tx * TN]);
            float4 b1 = *reinterpret_cast<const float4*>(&Bs[kk][tx * TN + 4]);
            float a[TM] = {a0.x, a0.y, a0.z, a0.w, a1.x, a1.y, a1.z, a1.w};
            float bb[TN] = {b0.x, b0.y, b0.z, b0.w, b1.x, b1.y, b1.z, b1.w};
#pragma unroll
            for (int i = 0; i < TM; i++)
#pragma unroll
                for (int j = 0; j < TN; j++) acc[i][j] += a[i] * bb[j];
        }
        __syncthreads();
    }

#pragma unroll
    for (int i = 0; i < TM; i++) {
        size_t off = ((size_t)b * S_ + q0 + ty * TM + i) * D_ + n0 + tx * TN;
        *reinterpret_cast<float4*>(&out[off]) =
            make_float4(acc[i][0], acc[i][1], acc[i][2], acc[i][3]);
        *reinterpret_cast<float4*>(&out[off + 4]) =
            make_float4(acc[i][4], acc[i][5], acc[i][6], acc[i][7]);
    }
}

// ---------------------------------------------------------------------------
extern "C" void kernel_launch(void* const* d_in, const int* in_sizes, int n_in,
                              void* d_out, int out_size) {
    const float* x  = (const float*)d_in[0];
    const float* wq = (const float*)d_in[1];
    const float* wk = (const float*)d_in[2];
    const float* wv = (const float*)d_in[3];
    float* out = (float*)d_out;

    rope_table_kernel<<<(S_ * HALF_D + 255) / 256, 256>>>();
    qkv_rope_kernel<<<dim3(D_ / BN, M_ / BM, 3), NTHREADS>>>(x, wq, wk, wv);
    scores_kernel<<<dim3(NTRI, B_, 1), NTHREADS>>>();
    softmax_kernel<<<B_ * S_, 256>>>();
    pv_kernel<<<dim3(D_ / BN, S_ / BM, B_), NTHREADS>>>(out);
}

// round 12
// speedup vs baseline: 2.8016x; 2.8016x over previous
#include <cuda_runtime.h>
#include <cuda_bf16.h>
#include <stdint.h>
#include <math.h>

// Problem constants
#define B_ 4
#define S_ 4096
#define D_ 1024
#define M_ (B_*S_)          // 16384 total rows
#define HALF_D (D_/2)       // 512 rope pairs

// GEMM tiling (tensor-core version)
#define BM 128
#define BN 128
#define BK 32
#define NTHREADS 256
#define SD 36                 // smem row stride (floats): 36%32=4 -> conflict-free frags
#define TILEF (128*SD)        // floats per smem tile
#define SMEM_BYTES (2*2*TILEF*4)   // 2 stages * (A+B) = 73728 bytes

// -------- scratch (static device globals; no allocation at runtime) --------
__device__ float g_q[(size_t)M_ * D_];          // 64 MB (rotated Q)
__device__ float g_k[(size_t)M_ * D_];          // 64 MB (rotated K)
__device__ float g_v[(size_t)M_ * D_];          // 64 MB
__device__ float g_vT[(size_t)B_ * D_ * S_];    // 64 MB (V transposed per batch)
__device__ float g_s[(size_t)B_ * S_ * S_];     // 256 MB (scores, then P in-place)
__device__ float g_cos[(size_t)S_ * HALF_D];    // 8 MB
__device__ float g_sin[(size_t)S_ * HALF_D];    // 8 MB

// ---------------------------------------------------------------------------
// PTX helpers
// ---------------------------------------------------------------------------
__device__ __forceinline__ uint32_t f2tf(float x) {
    uint32_t r;
    asm("cvt.rna.tf32.f32 %0, %1;" : "=r"(r) : "f"(x));
    return r;
}

__device__ __forceinline__ void mma_tf32(float* c, const uint32_t* a, const uint32_t* b) {
    asm volatile(
        "mma.sync.aligned.m16n8k8.row.col.f32.tf32.tf32.f32 "
        "{%0,%1,%2,%3}, {%4,%5,%6,%7}, {%8,%9}, {%0,%1,%2,%3};"
        : "+f"(c[0]), "+f"(c[1]), "+f"(c[2]), "+f"(c[3])
        : "r"(a[0]), "r"(a[1]), "r"(a[2]), "r"(a[3]), "r"(b[0]), "r"(b[1]));
}

__device__ __forceinline__ void cp16(void* s, const float* g) {
    uint32_t sa = (uint32_t)__cvta_generic_to_shared(s);
    asm volatile("cp.async.cg.shared.global [%0], [%1], 16;\n" :: "r"(sa), "l"(g));
}
__device__ __forceinline__ void cp_commit() { asm volatile("cp.async.commit_group;\n"); }
template<int N> __device__ __forceinline__ void cp_wait() {
    asm volatile("cp.async.wait_group %0;\n" :: "n"(N));
}

// ---------------------------------------------------------------------------
// Shared TF32 GEMM mainloop.
// A: [128 rows m][K] row-major (ldA), B: [128 rows n][K] row-major (ldB).
// Computes acc[mi][j][4] = A_tile * B_tile^T (i.e. C[m][n] = sum_k A[m,k]B[n,k]).
// Warp layout: 8 warps = 4(m) x 2(n); warp tile 32x64; mma m16n8k8.
// ---------------------------------------------------------------------------
__device__ __forceinline__ void gemm_loop(
    const float* __restrict__ Ag, const float* __restrict__ Bg,
    int ldA, int ldB, int iters, float acc[2][8][4], float* sm)
{
    const int tid  = threadIdx.x;
    const int lane = tid & 31;
    const int warp = tid >> 5;
    const int wm   = warp >> 1;      // 0..3
    const int wn   = warp & 1;       // 0..1
    const int gid  = lane >> 2;      // 0..7
    const int tig  = lane & 3;       // 0..3

    const int prow = tid >> 3;            // 0..31 base row pattern
    const int pslot = (tid & 7) * 4;      // k float4 slot

    // prefetch stage 0
    {
        float* sA = sm;
        float* sB = sm + TILEF;
#pragma unroll
        for (int l = 0; l < 4; l++) {
            int row = prow + l * 32;
            cp16(sA + row * SD + pslot, Ag + (size_t)row * ldA + pslot);
            cp16(sB + row * SD + pslot, Bg + (size_t)row * ldB + pslot);
        }
        cp_commit();
    }

    for (int it = 0; it < iters; it++) {
        const int buf = it & 1;
        if (it + 1 < iters) {
            float* sA = sm + (buf ^ 1) * 2 * TILEF;
            float* sB = sA + TILEF;
            const int k0 = (it + 1) * BK;
#pragma unroll
            for (int l = 0; l < 4; l++) {
                int row = prow + l * 32;
                cp16(sA + row * SD + pslot, Ag + (size_t)row * ldA + k0 + pslot);
                cp16(sB + row * SD + pslot, Bg + (size_t)row * ldB + k0 + pslot);
            }
            cp_commit();
            cp_wait<1>();
        } else {
            cp_wait<0>();
        }
        __syncthreads();

        const float* sA = sm + buf * 2 * TILEF;
        const float* sB = sA + TILEF;
        const float* aBase = sA + (wm * 32 + gid) * SD + tig;
        const float* bBase = sB + (wn * 64 + gid) * SD + tig;

#pragma unroll
        for (int ks = 0; ks < 4; ks++) {
            const int kb = ks * 8;
            uint32_t Af[2][4];
#pragma unroll
            for (int mi = 0; mi < 2; mi++) {
                const float* p = aBase + mi * 16 * SD + kb;
                Af[mi][0] = f2tf(p[0]);
                Af[mi][1] = f2tf(p[8 * SD]);
                Af[mi][2] = f2tf(p[4]);
                Af[mi][3] = f2tf(p[8 * SD + 4]);
            }
            uint32_t Bf[8][2];
#pragma unroll
            for (int j = 0; j < 8; j++) {
                const float* p = bBase + j * 8 * SD + kb;
                Bf[j][0] = f2tf(p[0]);
                Bf[j][1] = f2tf(p[4]);
            }
#pragma unroll
            for (int mi = 0; mi < 2; mi++)
#pragma unroll
                for (int j = 0; j < 8; j++)
                    mma_tf32(acc[mi][j], Af[mi], Bf[j]);
        }
        __syncthreads();
    }
}

// ---------------------------------------------------------------------------
// Kernel 0: RoPE cos/sin table.
// theta = 10000 ** (-2*(i-1)/d)  (faithful to the reference's i-1).
// Angle rounded to fp32 exactly as the reference (pos_f32 * theta_f32),
// then range-reduced in double so sinf/cosf stay accurate under fast-math.
// ---------------------------------------------------------------------------
__global__ __launch_bounds__(256) void rope_table_kernel() {
    int idx = blockIdx.x * 256 + threadIdx.x;
    if (idx >= S_ * HALF_D) return;
    int pos = idx / HALF_D;
    int i   = idx % HALF_D;
    double ex    = (-2.0 * ((double)i - 1.0)) / (double)D_;
    double theta = exp(ex * 9.210340371976184);          // ln(10000)
    float  thetaf = (float)theta;
    float  angf   = (float)pos * thetaf;                  // fp32, like reference
    double r = fmod((double)angf, 6.283185307179586477);
    float  rf = (float)r;
    if (rf > 3.14159265358979f) rf -= 6.28318530717959f;
    g_cos[idx] = cosf(rf);
    g_sin[idx] = sinf(rf);
}

// ---------------------------------------------------------------------------
// Kernel 1: fused QKV projection (TF32 MMA) + RoPE epilogue for Q/K.
// blockIdx.z: 0->Q(+rope), 1->K(+rope), 2->V
// ---------------------------------------------------------------------------
__global__ __launch_bounds__(NTHREADS) void qkv_tc_kernel(
    const float* __restrict__ x, const float* __restrict__ wq,
    const float* __restrict__ wk, const float* __restrict__ wv)
{
    extern __shared__ float sm[];
    const int which = blockIdx.z;
    const float* __restrict__ w = (which == 0) ? wq : (which == 1) ? wk : wv;
    float* __restrict__ out     = (which == 0) ? g_q : (which == 1) ? g_k : g_v;

    const int m0 = blockIdx.y * BM;
    const int n0 = blockIdx.x * BN;

    float acc[2][8][4];
#pragma unroll
    for (int mi = 0; mi < 2; mi++)
#pragma unroll
        for (int j = 0; j < 8; j++)
#pragma unroll
            for (int t = 0; t < 4; t++) acc[mi][j][t] = 0.f;

    gemm_loop(x + (size_t)m0 * D_, w + (size_t)n0 * D_, D_, D_, D_ / BK, acc, sm);

    const int lane = threadIdx.x & 31;
    const int warp = threadIdx.x >> 5;
    const int wm = warp >> 1, wn = warp & 1;
    const int gid = lane >> 2, tig = lane & 3;

#pragma unroll
    for (int mi = 0; mi < 2; mi++) {
#pragma unroll
        for (int j = 0; j < 8; j++) {
            int row = m0 + wm * 32 + mi * 16 + gid;
            int col = n0 + wn * 64 + j * 8 + tig * 2;
            float2 v01 = make_float2(acc[mi][j][0], acc[mi][j][1]);
            float2 v23 = make_float2(acc[mi][j][2], acc[mi][j][3]);
            if (which < 2) {
                int ip = col >> 1;
                int pos0 = row & (S_ - 1);
                int pos1 = (row + 8) & (S_ - 1);
                float c0 = g_cos[(size_t)pos0 * HALF_D + ip];
                float s0 = g_sin[(size_t)pos0 * HALF_D + ip];
                float c1 = g_cos[(size_t)pos1 * HALF_D + ip];
                float s1 = g_sin[(size_t)pos1 * HALF_D + ip];
                float e = v01.x, o = v01.y;
                v01.x =  e * c0 + o * s0;
                v01.y = -e * s0 + o * c0;
                e = v23.x; o = v23.y;
                v23.x =  e * c1 + o * s1;
                v23.y = -e * s1 + o * c1;
            }
            *reinterpret_cast<float2*>(&out[(size_t)row * D_ + col]) = v01;
            *reinterpret_cast<float2*>(&out[(size_t)(row + 8) * D_ + col]) = v23;
        }
    }
}

// ---------------------------------------------------------------------------
// Kernel 1b: transpose V per batch: g_v [b][s][d] -> g_vT [b][d][s]
// ---------------------------------------------------------------------------
__global__ __launch_bounds__(256) void transpose_v_kernel() {
    __shared__ float t[32][33];
    const int b  = blockIdx.z;
    const int d0 = blockIdx.x * 32;
    const int s0 = blockIdx.y * 32;
    const int tx = threadIdx.x & 31;
    const int ty = threadIdx.x >> 5;   // 0..7
#pragma unroll
    for (int i = 0; i < 4; i++) {
        int s = ty + i * 8;
        t[s][tx] = g_v[((size_t)b * S_ + s0 + s) * D_ + d0 + tx];
    }
    __syncthreads();
#pragma unroll
    for (int i = 0; i < 4; i++) {
        int d = ty + i * 8;
        g_vT[((size_t)b * D_ + d0 + d) * S_ + s0 + tx] = t[tx][d];
    }
}

// ---------------------------------------------------------------------------
// Kernel 2: causal scores (TF32 MMA). Lower-triangular tiles only.
// ---------------------------------------------------------------------------
#define NTRI ((S_/BM) * (S_/BM + 1) / 2)   // 528 tiles per batch

__global__ __launch_bounds__(NTHREADS) void scores_tc_kernel() {
    extern __shared__ float sm[];
    const int idx = blockIdx.x;
    const int b   = blockIdx.y;
    int qt = (int)((sqrtf(8.f * (float)idx + 1.f) - 1.f) * 0.5f);
    while ((qt + 1) * (qt + 2) / 2 <= idx) qt++;
    while (qt * (qt + 1) / 2 > idx) qt--;
    const int kt = idx - qt * (qt + 1) / 2;

    const int m0 = qt * BM;
    const int n0 = kt * BN;
    const float* __restrict__ Qb = g_q + (size_t)b * S_ * D_ + (size_t)m0 * D_;
    const float* __restrict__ Kb = g_k + (size_t)b * S_ * D_ + (size_t)n0 * D_;

    float acc[2][8][4];
#pragma unroll
    for (int mi = 0; mi < 2; mi++)
#pragma unroll
        for (int j = 0; j < 8; j++)
#pragma unroll
            for (int t = 0; t < 4; t++) acc[mi][j][t] = 0.f;

    gemm_loop(Qb, Kb, D_, D_, D_ / BK, acc, sm);

    const int lane = threadIdx.x & 31;
    const int warp = threadIdx.x >> 5;
    const int wm = warp >> 1, wn = warp & 1;
    const int gid = lane >> 2, tig = lane & 3;

    const float scale = 0.03125f;   // 1/sqrt(1024)
    float* Sb = g_s + (size_t)b * S_ * S_;
#pragma unroll
    for (int mi = 0; mi < 2; mi++) {
#pragma unroll
        for (int j = 0; j < 8; j++) {
            int row = m0 + wm * 32 + mi * 16 + gid;
            int col = n0 + wn * 64 + j * 8 + tig * 2;
            float2 v01, v23;
            v01.x = (col     > row    ) ? -1e30f : acc[mi][j][0] * scale;
            v01.y = (col + 1 > row    ) ? -1e30f : acc[mi][j][1] * scale;
            v23.x = (col     > row + 8) ? -1e30f : acc[mi][j][2] * scale;
            v23.y = (col + 1 > row + 8) ? -1e30f : acc[mi][j][3] * scale;
            *reinterpret_cast<float2*>(&Sb[(size_t)row * S_ + col]) = v01;
            *reinterpret_cast<float2*>(&Sb[(size_t)(row + 8) * S_ + col]) = v23;
        }
    }
}

// ---------------------------------------------------------------------------
// Kernel 3: per-row softmax, in place. Masked entries (-1e30) underflow to
// exact 0.0, which zero-pads the diagonal tile for the PV GEMM's 128-aligned
// K bound.
// ---------------------------------------------------------------------------
__global__ __launch_bounds__(256) void softmax_kernel() {
    const int rowid = blockIdx.x;
    const int b = rowid >> 12;
    const int q = rowid & (S_ - 1);
    float* srow = g_s + (size_t)b * S_ * S_ + (size_t)q * S_;
    const int kmax = ((q >> 7) + 1) << 7;
    const int tid = threadIdx.x;

    float vals[16];
    int nch = 0;
    float mx = -1e30f;
    for (int c = tid * 4; c < kmax; c += 1024) {
        float4 v = *reinterpret_cast<const float4*>(&srow[c]);
        vals[nch * 4 + 0] = v.x; vals[nch * 4 + 1] = v.y;
        vals[nch * 4 + 2] = v.z; vals[nch * 4 + 3] = v.w;
        mx = fmaxf(mx, fmaxf(fmaxf(v.x, v.y), fmaxf(v.z, v.w)));
        nch++;
    }

    __shared__ float red[256];
    red[tid] = mx;
    __syncthreads();
    for (int off = 128; off > 0; off >>= 1) {
        if (tid < off) red[tid] = fmaxf(red[tid], red[tid + off]);
        __syncthreads();
    }
    const float m = red[0];
    __syncthreads();

    float sum = 0.f;
    for (int t = 0; t < nch * 4; t++) {
        vals[t] = __expf(vals[t] - m);
        sum += vals[t];
    }
    red[tid] = sum;
    __syncthreads();
    for (int off = 128; off > 0; off >>= 1) {
        if (tid < off) red[tid] += red[tid + off];
        __syncthreads();
    }
    const float invl = 1.f / red[0];

    int ch = 0;
    for (int c = tid * 4; c < kmax; c += 1024) {
        float4 o = make_float4(vals[ch * 4 + 0] * invl, vals[ch * 4 + 1] * invl,
                               vals[ch * 4 + 2] * invl, vals[ch * 4 + 3] * invl);
        *reinterpret_cast<float4*>(&srow[c]) = o;
        ch++;
    }
}

// ---------------------------------------------------------------------------
// Kernel 4: O = P @ V (TF32 MMA), causal K bound per query tile.
// B operand is g_vT (row-major [d][s] => col-major V), k-contiguous.
// ---------------------------------------------------------------------------
__global__ __launch_bounds__(NTHREADS) void pv_tc_kernel(float* __restrict__ out) {
    extern __shared__ float sm[];
    const int b  = blockIdx.z;
    const int q0 = blockIdx.y * BM;
    const int n0 = blockIdx.x * BN;
    const int iters = (q0 + BM) / BK;

    const float* __restrict__ P  = g_s  + (size_t)b * S_ * S_ + (size_t)q0 * S_;
    const float* __restrict__ Vt = g_vT + (size_t)b * D_ * S_ + (size_t)n0 * S_;

    float acc[2][8][4];
#pragma unroll
    for (int mi = 0; mi < 2; mi++)
#pragma unroll
        for (int j = 0; j < 8; j++)
#pragma unroll
            for (int t = 0; t < 4; t++) acc[mi][j][t] = 0.f;

    gemm_loop(P, Vt, S_, S_, iters, acc, sm);

    const int lane = threadIdx.x & 31;
    const int warp = threadIdx.x >> 5;
    const int wm = warp >> 1, wn = warp & 1;
    const int gid = lane >> 2, tig = lane & 3;

#pragma unroll
    for (int mi = 0; mi < 2; mi++) {
#pragma unroll
        for (int j = 0; j < 8; j++) {
            int row = q0 + wm * 32 + mi * 16 + gid;
            int col = n0 + wn * 64 + j * 8 + tig * 2;
            float2 v01 = make_float2(acc[mi][j][0], acc[mi][j][1]);
            float2 v23 = make_float2(acc[mi][j][2], acc[mi][j][3]);
            *reinterpret_cast<float2*>(&out[((size_t)b * S_ + row) * D_ + col]) = v01;
            *reinterpret_cast<float2*>(&out[((size_t)b * S_ + row + 8) * D_ + col]) = v23;
        }
    }
}

// ---------------------------------------------------------------------------
extern "C" void kernel_launch(void* const* d_in, const int* in_sizes, int n_in,
                              void* d_out, int out_size) {
    const float* x  = (const float*)d_in[0];
    const float* wq = (const float*)d_in[1];
    const float* wk = (const float*)d_in[2];
    const float* wv = (const float*)d_in[3];
    float* out = (float*)d_out;

    cudaFuncSetAttribute(qkv_tc_kernel,    cudaFuncAttributeMaxDynamicSharedMemorySize, SMEM_BYTES);
    cudaFuncSetAttribute(scores_tc_kernel, cudaFuncAttributeMaxDynamicSharedMemorySize, SMEM_BYTES);
    cudaFuncSetAttribute(pv_tc_kernel,     cudaFuncAttributeMaxDynamicSharedMemorySize, SMEM_BYTES);

    rope_table_kernel<<<(S_ * HALF_D + 255) / 256, 256>>>();
    qkv_tc_kernel<<<dim3(D_ / BN, M_ / BM, 3), NTHREADS, SMEM_BYTES>>>(x, wq, wk, wv);
    transpose_v_kernel<<<dim3(D_ / 32, S_ / 32, B_), 256>>>();
    scores_tc_kernel<<<dim3(NTRI, B_, 1), NTHREADS, SMEM_BYTES>>>();
    softmax_kernel<<<B_ * S_, 256>>>();
    pv_tc_kernel<<<dim3(D_ / BN, S_ / BM, B_), NTHREADS, SMEM_BYTES>>>(out);
}